// round 16
// baseline (speedup 1.0000x reference)
#include <cuda_runtime.h>
#include <math.h>

#define BI 256
#define BC 256
#define TT 64
#define DD 1024
#define DR 256
#define LREG 36
#define EPSN 1e-8f
#define KSPLIT_CC 4
#define KC_CC (DD / KSPLIT_CC)   // 256
#define KSPLIT_S 8
#define KC_S (DD / KSPLIT_S)     // 128
#define CCSZ (BI * 3 * DD)

// ---------------- scratch (no allocations allowed) ----------------
__device__ float g_cap_v[BC * DD];
__device__ float g_w[BC * 3];
__device__ float g_t[BC];
__device__ float g_P[BI * 3 * DD];
__device__ float g_CCpart[KSPLIT_CC][CCSZ];
__device__ float g_CC[CCSZ];
__device__ float g_Spart[KSPLIT_S][BI * 3 * BC];
__device__ float g_qpart[2 * 3 * DD];
__device__ float g_c[3];

// ---------------- f32x2 packed FMA helpers ----------------
static __device__ __forceinline__ void fma2(unsigned long long& d,
                                            unsigned long long a,
                                            unsigned long long b) {
    asm("fma.rn.f32x2 %0, %1, %2, %0;" : "+l"(d) : "l"(a), "l"(b));
}
static __device__ __forceinline__ unsigned long long dup(float x) {
    unsigned long long r;
    asm("mov.b64 %0, {%1, %1};" : "=l"(r) : "f"(x));
    return r;
}
static __device__ __forceinline__ float2 unpk(unsigned long long v) {
    float2 r;
    asm("mov.b64 {%0, %1}, %2;" : "=f"(r.x), "=f"(r.y) : "l"(v));
    return r;
}
static __device__ __forceinline__ float dot4(float4 a, float4 b) {
    return a.x * b.x + a.y * b.y + a.z * b.z + a.w * b.w;
}

// ---------------- kernel 0: q[k] = red_w^T @ proj_w[k]  (e-split x2), c[k] ----------------
__global__ __launch_bounds__(256) void prep_q(const float* __restrict__ red_w,
                                              const float* __restrict__ red_b,
                                              const float* __restrict__ proj_w,
                                              const float* __restrict__ proj_b,
                                              float* __restrict__ qpart,
                                              float* __restrict__ c) {
    const int part = blockIdx.x >> 2;
    const int d = (blockIdx.x & 3) * 256 + threadIdx.x;
    const int e0 = part * (DR / 2);
    float a0 = 0.f, a1 = 0.f, a2 = 0.f;
#pragma unroll 16
    for (int e = e0; e < e0 + DR / 2; e++) {
        float r = __ldg(red_w + (size_t)e * DD + d);
        a0 += r * proj_w[e];
        a1 += r * proj_w[DR + e];
        a2 += r * proj_w[2 * DR + e];
    }
    qpart[part * 3 * DD + 0 * DD + d] = a0;
    qpart[part * 3 * DD + 1 * DD + d] = a1;
    qpart[part * 3 * DD + 2 * DD + d] = a2;

    if (blockIdx.x == 0 && threadIdx.x < 32) {
        int l = threadIdx.x;
        float c0 = 0.f, c1 = 0.f, c2 = 0.f;
#pragma unroll
        for (int j = 0; j < DR / 32; j++) {
            int e = l + j * 32;
            float rb = red_b[e];
            c0 += rb * proj_w[e];
            c1 += rb * proj_w[DR + e];
            c2 += rb * proj_w[2 * DR + e];
        }
#pragma unroll
        for (int off = 16; off > 0; off >>= 1) {
            c0 += __shfl_xor_sync(0xffffffffu, c0, off);
            c1 += __shfl_xor_sync(0xffffffffu, c1, off);
            c2 += __shfl_xor_sync(0xffffffffu, c2, off);
        }
        if (l == 0) {
            c[0] = c0 + proj_b[0];
            c[1] = c1 + proj_b[1];
            c[2] = c2 + proj_b[2];
        }
    }
}

// ---------------- fused input reductions + softmax filter ----------------
__global__ __launch_bounds__(256) void pre_reduce(const float* __restrict__ cap,
                                                  const int* __restrict__ lens,
                                                  const float* __restrict__ img,
                                                  const float* __restrict__ conv_b,
                                                  const float* __restrict__ qpart,
                                                  const float* __restrict__ c,
                                                  float* __restrict__ cap_v,
                                                  float* __restrict__ w_out,
                                                  float* __restrict__ t_out,
                                                  float* __restrict__ P) {
    int tid = threadIdx.x;
    if (blockIdx.x < BC) {
        int b = blockIdx.x;
        int len = __ldg(lens + b);
        const float4* row = (const float4*)(cap + (size_t)b * TT * DD);
        float4 acc = make_float4(0.f, 0.f, 0.f, 0.f);
#pragma unroll 8
        for (int t = 0; t < len; t++) {
            float4 v = row[t * (DD / 4) + tid];
            acc.x += v.x; acc.y += v.y; acc.z += v.z; acc.w += v.w;
        }
        float inv = 1.0f / (float)len;
        acc.x *= inv; acc.y *= inv; acc.z *= inv; acc.w *= inv;

        const float4* qA = (const float4*)qpart;
        const float4* qB = (const float4*)(qpart + 3 * DD);
        const float4* cb4 = (const float4*)conv_b;
        float ss = dot4(acc, acc);
        float p0 = dot4(acc, qA[0 * (DD / 4) + tid]) + dot4(acc, qB[0 * (DD / 4) + tid]);
        float p1 = dot4(acc, qA[1 * (DD / 4) + tid]) + dot4(acc, qB[1 * (DD / 4) + tid]);
        float p2 = dot4(acc, qA[2 * (DD / 4) + tid]) + dot4(acc, qB[2 * (DD / 4) + tid]);
        float tb = dot4(acc, cb4[tid]);
#pragma unroll
        for (int off = 16; off > 0; off >>= 1) {
            ss += __shfl_xor_sync(0xffffffffu, ss, off);
            p0 += __shfl_xor_sync(0xffffffffu, p0, off);
            p1 += __shfl_xor_sync(0xffffffffu, p1, off);
            p2 += __shfl_xor_sync(0xffffffffu, p2, off);
            tb += __shfl_xor_sync(0xffffffffu, tb, off);
        }
        __shared__ float sw[8][5];
        __shared__ float sinv;
        if ((tid & 31) == 0) {
            int w = tid >> 5;
            sw[w][0] = ss; sw[w][1] = p0; sw[w][2] = p1; sw[w][3] = p2; sw[w][4] = tb;
        }
        __syncthreads();
        if (tid == 0) {
            float tss = 0.f, tp0 = 0.f, tp1 = 0.f, tp2 = 0.f, ttb = 0.f;
#pragma unroll
            for (int w = 0; w < 8; w++) {
                tss += sw[w][0]; tp0 += sw[w][1]; tp1 += sw[w][2];
                tp2 += sw[w][3]; ttb += sw[w][4];
            }
            float si = 1.0f / (sqrtf(tss) + EPSN);
            sinv = si;
            float l0 = tp0 + c[0], l1 = tp1 + c[1], l2 = tp2 + c[2];
            float mx = fmaxf(l0, fmaxf(l1, l2));
            float e0 = expf(l0 - mx), e1 = expf(l1 - mx), e2 = expf(l2 - mx);
            float einv = 1.0f / (e0 + e1 + e2);
            w_out[b * 3 + 0] = e0 * einv;
            w_out[b * 3 + 1] = e1 * einv;
            w_out[b * 3 + 2] = e2 * einv;
            t_out[b] = ttb * si;
        }
        __syncthreads();
        float si = sinv;
        float4 nv = make_float4(acc.x * si, acc.y * si, acc.z * si, acc.w * si);
        ((float4*)(cap_v + (size_t)b * DD))[tid] = nv;
    } else {
        int i = blockIdx.x - BC;
        const float4* base = (const float4*)(img + (size_t)i * LREG * DD);
        float4 s = make_float4(0.f, 0.f, 0.f, 0.f);
        float4 r0 = make_float4(0.f, 0.f, 0.f, 0.f);
        float4 r35 = make_float4(0.f, 0.f, 0.f, 0.f);
#pragma unroll 4
        for (int t = 0; t < LREG; t++) {
            float4 v = base[t * (DD / 4) + tid];
            if (t == 0) r0 = v;
            if (t == LREG - 1) r35 = v;
            s.x += v.x; s.y += v.y; s.z += v.z; s.w += v.w;
        }
        const float invL = 1.0f / (float)LREG;
        float4 p0 = make_float4((s.x - r35.x) * invL, (s.y - r35.y) * invL,
                                (s.z - r35.z) * invL, (s.w - r35.w) * invL);
        float4 p1 = make_float4(s.x * invL, s.y * invL, s.z * invL, s.w * invL);
        float4 p2 = make_float4((s.x - r0.x) * invL, (s.y - r0.y) * invL,
                                (s.z - r0.z) * invL, (s.w - r0.w) * invL);
        ((float4*)(P + (size_t)(i * 3 + 0) * DD))[tid] = p0;
        ((float4*)(P + (size_t)(i * 3 + 1) * DD))[tid] = p1;
        ((float4*)(P + (size_t)(i * 3 + 2) * DD))[tid] = p2;
    }
}

// ---------------- GEMM: C[m,n] = sum_k A[m,k]*B[n,k] (A: MxK, B: NxK, row-major) ----------------
// 64x64 tile, BK=32, 128 threads, 4m x 8n micro-tile. A stored UNduplicated in smem
// (1 LDS.128) and duplicated in registers via mov.b64 (ALU pipe idle); B as 2 LDS.128.
// 48 smem bytes / 32 MACs = 1.5 B/MAC (2x better than prior 3 B/MAC — measured smem-BW-bound).
// 2-stage double buffering; split-K along gridDim.z into per-partition buffers.
__global__ __launch_bounds__(128) void gemm_s(const float* __restrict__ A,
                                              const float* __restrict__ B,
                                              float* __restrict__ C,
                                              int M, int N, int K, int KCsz) {
    __shared__ __align__(16) float As[2][32][68];  // 68*4=272B row stride (16B multiple)
    __shared__ __align__(16) float Bs[2][32][68];
    const int bm = blockIdx.y * 64, bn = blockIdx.x * 64;
    const int kbase = blockIdx.z * KCsz;
    float* Cz = C + (size_t)blockIdx.z * M * N;
    const int tid = threadIdx.x;
    const int tn = tid & 7, tm = tid >> 3;   // tn 0..7, tm 0..15
    const int n0 = tn * 8, m0 = tm * 4;
    const int lrow = tid >> 1;               // 0..63
    const int lk = (tid & 1) * 16;           // k-half 0 or 16

    unsigned long long acc[4][4];
#pragma unroll
    for (int i = 0; i < 4; i++)
#pragma unroll
        for (int j = 0; j < 4; j++) acc[i][j] = 0ULL;

    const float* Ap = A + (size_t)(bm + lrow) * K + kbase + lk;
    const float* Bp = B + (size_t)(bn + lrow) * K + kbase + lk;

    const int T = KCsz / 32;

    // prologue: fill buffer 0
    {
#pragma unroll
        for (int j = 0; j < 4; j++) {
            float4 va = *(const float4*)(Ap + 4 * j);
            float4 vb = *(const float4*)(Bp + 4 * j);
            As[0][lk + 4 * j + 0][lrow] = va.x;
            As[0][lk + 4 * j + 1][lrow] = va.y;
            As[0][lk + 4 * j + 2][lrow] = va.z;
            As[0][lk + 4 * j + 3][lrow] = va.w;
            Bs[0][lk + 4 * j + 0][lrow] = vb.x;
            Bs[0][lk + 4 * j + 1][lrow] = vb.y;
            Bs[0][lk + 4 * j + 2][lrow] = vb.z;
            Bs[0][lk + 4 * j + 3][lrow] = vb.w;
        }
    }
    __syncthreads();

    for (int t = 0; t < T; t++) {
        float4 pa[4], pb[4];
        if (t + 1 < T) {
            int off = (t + 1) * 32;
#pragma unroll
            for (int j = 0; j < 4; j++) {
                pa[j] = *(const float4*)(Ap + off + 4 * j);
                pb[j] = *(const float4*)(Bp + off + 4 * j);
            }
        }
        const int buf = t & 1;
#pragma unroll
        for (int kk = 0; kk < 32; kk++) {
            float4 av = *(const float4*)&As[buf][kk][m0];
            ulonglong2 b01 = *(const ulonglong2*)&Bs[buf][kk][n0];
            ulonglong2 b23 = *(const ulonglong2*)&Bs[buf][kk][n0 + 4];
            unsigned long long a0 = dup(av.x), a1 = dup(av.y);
            unsigned long long a2 = dup(av.z), a3 = dup(av.w);
            fma2(acc[0][0], a0, b01.x); fma2(acc[0][1], a0, b01.y);
            fma2(acc[0][2], a0, b23.x); fma2(acc[0][3], a0, b23.y);
            fma2(acc[1][0], a1, b01.x); fma2(acc[1][1], a1, b01.y);
            fma2(acc[1][2], a1, b23.x); fma2(acc[1][3], a1, b23.y);
            fma2(acc[2][0], a2, b01.x); fma2(acc[2][1], a2, b01.y);
            fma2(acc[2][2], a2, b23.x); fma2(acc[2][3], a2, b23.y);
            fma2(acc[3][0], a3, b01.x); fma2(acc[3][1], a3, b01.y);
            fma2(acc[3][2], a3, b23.x); fma2(acc[3][3], a3, b23.y);
        }
        if (t + 1 < T) {
            const int nb = (t + 1) & 1;
#pragma unroll
            for (int j = 0; j < 4; j++) {
                As[nb][lk + 4 * j + 0][lrow] = pa[j].x;
                As[nb][lk + 4 * j + 1][lrow] = pa[j].y;
                As[nb][lk + 4 * j + 2][lrow] = pa[j].z;
                As[nb][lk + 4 * j + 3][lrow] = pa[j].w;
                Bs[nb][lk + 4 * j + 0][lrow] = pb[j].x;
                Bs[nb][lk + 4 * j + 1][lrow] = pb[j].y;
                Bs[nb][lk + 4 * j + 2][lrow] = pb[j].z;
                Bs[nb][lk + 4 * j + 3][lrow] = pb[j].w;
            }
            __syncthreads();
        }
    }
#pragma unroll
    for (int i = 0; i < 4; i++) {
        float2 f0 = unpk(acc[i][0]);
        float2 f1 = unpk(acc[i][1]);
        float2 f2 = unpk(acc[i][2]);
        float2 f3 = unpk(acc[i][3]);
        float4 o0 = make_float4(f0.x, f0.y, f1.x, f1.y);
        float4 o1 = make_float4(f2.x, f2.y, f3.x, f3.y);
        float* crow = Cz + (size_t)(bm + m0 + i) * N + bn + n0;
        *(float4*)(crow) = o0;
        *(float4*)(crow + 4) = o1;
    }
}

// ---------------- sum the KSPLIT_CC partial CC buffers ----------------
__global__ __launch_bounds__(256) void cc_sum(const float* __restrict__ CCp,
                                              float* __restrict__ CC) {
    size_t idx = ((size_t)blockIdx.x * 256 + threadIdx.x) * 4;
    float4 a = *(const float4*)(CCp + idx);
    float4 b = *(const float4*)(CCp + (size_t)CCSZ + idx);
    float4 c = *(const float4*)(CCp + 2 * (size_t)CCSZ + idx);
    float4 d = *(const float4*)(CCp + 3 * (size_t)CCSZ + idx);
    float4 o = make_float4(a.x + b.x + c.x + d.x, a.y + b.y + c.y + d.y,
                           a.z + b.z + c.z + d.z, a.w + b.w + c.w + d.w);
    *(float4*)(CC + idx) = o;
}

// ---------------- fused kernel: per-image Gram + split-K sum + final similarity ----------------
__global__ __launch_bounds__(256) void final_kernel(const float* __restrict__ CC,
                                                    const float* __restrict__ conv_b,
                                                    const float* __restrict__ Spart,
                                                    const float* __restrict__ W,
                                                    const float* __restrict__ T_,
                                                    float* __restrict__ out) {
    int i = blockIdx.x;
    int tid = threadIdx.x;

    const float4* c0 = (const float4*)(CC + (size_t)(i * 3 + 0) * DD);
    const float4* c1 = (const float4*)(CC + (size_t)(i * 3 + 1) * DD);
    const float4* c2 = (const float4*)(CC + (size_t)(i * 3 + 2) * DD);
    const float4* cb = (const float4*)conv_b;
    float4 v0 = c0[tid], v1 = c1[tid], v2 = c2[tid], vb = cb[tid];
    float p[10];
    p[0] = dot4(v0, v0); p[1] = dot4(v0, v1); p[2] = dot4(v0, v2);
    p[3] = dot4(v0, vb); p[4] = dot4(v1, v1); p[5] = dot4(v1, v2);
    p[6] = dot4(v1, vb); p[7] = dot4(v2, v2); p[8] = dot4(v2, vb);
    p[9] = dot4(vb, vb);
#pragma unroll
    for (int q = 0; q < 10; q++) {
#pragma unroll
        for (int off = 16; off > 0; off >>= 1)
            p[q] += __shfl_xor_sync(0xffffffffu, p[q], off);
    }
    __shared__ float sp[8][10];
    if ((tid & 31) == 0) {
        int w = tid >> 5;
#pragma unroll
        for (int q = 0; q < 10; q++) sp[w][q] = p[q];
    }
    __syncthreads();
    __shared__ float sG[10];
    if (tid < 10) {
        float s = 0.f;
#pragma unroll
        for (int w = 0; w < 8; w++) s += sp[w][tid];
        sG[tid] = s;
    }
    __syncthreads();

    int b = tid;
    float w0 = W[b * 3 + 0], w1 = W[b * 3 + 1], w2 = W[b * 3 + 2];
    float s0 = 0.f, s1 = 0.f, s2 = 0.f;
#pragma unroll
    for (int z = 0; z < KSPLIT_S; z++) {
        const float* Sz = Spart + (size_t)z * (BI * 3 * BC);
        s0 += Sz[(size_t)(i * 3 + 0) * BC + b];
        s1 += Sz[(size_t)(i * 3 + 1) * BC + b];
        s2 += Sz[(size_t)(i * 3 + 2) * BC + b];
    }
    float num = w0 * s0 + w1 * s1 + w2 * s2 + T_[b];
    float quad = w0 * w0 * sG[0] + w1 * w1 * sG[4] + w2 * w2 * sG[7] + sG[9] +
                 2.0f * (w0 * w1 * sG[1] + w0 * w2 * sG[2] + w0 * sG[3] +
                         w1 * w2 * sG[5] + w1 * sG[6] + w2 * sG[8]);
    out[(size_t)i * BC + b] = num / (sqrtf(quad) + EPSN);
}

// ---------------- host launcher ----------------
extern "C" void kernel_launch(void* const* d_in, const int* in_sizes, int n_in,
                              void* d_out, int out_size) {
    const float* img = (const float*)d_in[0];
    const float* cap = (const float*)d_in[1];
    const int* lens = (const int*)d_in[2];
    const float* red_w = (const float*)d_in[3];
    const float* red_b = (const float*)d_in[4];
    const float* proj_w = (const float*)d_in[5];
    const float* proj_b = (const float*)d_in[6];
    const float* conv_w = (const float*)d_in[7];
    const float* conv_b = (const float*)d_in[8];
    float* out = (float*)d_out;

    float *capV, *W, *T_, *P, *CCp, *CC, *SP, *QP, *Cc;
    cudaGetSymbolAddress((void**)&capV, g_cap_v);
    cudaGetSymbolAddress((void**)&W, g_w);
    cudaGetSymbolAddress((void**)&T_, g_t);
    cudaGetSymbolAddress((void**)&P, g_P);
    cudaGetSymbolAddress((void**)&CCp, g_CCpart);
    cudaGetSymbolAddress((void**)&CC, g_CC);
    cudaGetSymbolAddress((void**)&SP, g_Spart);
    cudaGetSymbolAddress((void**)&QP, g_qpart);
    cudaGetSymbolAddress((void**)&Cc, g_c);

    // q = red_w^T @ proj_w (e-split x2), c = red_b . proj_w + proj_b
    prep_q<<<8, 256>>>(red_w, red_b, proj_w, proj_b, QP, Cc);
    // fused caption mean/l2norm/softmax-w/t + image pooling
    pre_reduce<<<BC + BI, 256>>>(cap, lens, img, conv_b, QP, Cc, capV, W, T_, P);
    // CC = P @ conv_w^T (768x1024, K=1024): 16 x 12 x 4 = 768 blocks, split-K partials
    gemm_s<<<dim3(DD / 64, (BI * 3) / 64, KSPLIT_CC), 128>>>(P, conv_w, CCp,
                                                             BI * 3, DD, DD, KC_CC);
    // sum CC partials
    cc_sum<<<CCSZ / 4 / 256, 256>>>(CCp, CC);
    // S = CC @ cap_v^T (768x256, K=1024): 4 x 12 x 8 = 384 blocks, split-K partials
    gemm_s<<<dim3(BC / 64, (BI * 3) / 64, KSPLIT_S), 128>>>(CC, capV, SP,
                                                            BI * 3, BC, DD, KC_S);
    // fused Gram + split-K sum + final similarity
    final_kernel<<<BI, 256>>>(CC, conv_b, SP, W, T_, out);
}